// round 7
// baseline (speedup 1.0000x reference)
#include <cuda_runtime.h>
#include <cuda_fp16.h>
#include <cstdint>
#include <math.h>

#define NB 16
#define CI 512
#define CO 512
#define SD 512

// ---------------------------------------------------------------------------
// Scratch (__device__ globals — allowed)
__device__ float g_s[NB * CI];
__device__ float g_W2[CO * CI];
__device__ float g_alpha[NB * CO];
__device__ __half g_x[(size_t)NB * 32 * 32 * CI];   // [b][y][x][i] fp16, modulated
__device__ __half g_k[(size_t)9 * CO * CI];         // [tap][o][i] fp16
__device__ __half g_z[(size_t)NB * CO * 9 * 1024];  // [b][o][tap][32x32] fp16

// (upsample-2 transposed k3) ∘ (blur [1,3,3,1]/4) composition, per parity
__constant__ float c_M[2][3][3] = {
    {{0.00f, 0.25f, 0.75f}, {0.75f, 0.75f, 0.25f}, {0.25f, 0.00f, 0.00f}},
    {{0.00f, 0.00f, 0.25f}, {0.25f, 0.75f, 0.75f}, {0.75f, 0.25f, 0.00f}}
};

// ---------------------------------------------------------------------------
__device__ __forceinline__ unsigned h2u(__half2 h) {
    return *reinterpret_cast<unsigned*>(&h);
}
__device__ __forceinline__ uint32_t smem_u32(const void* p) {
    uint32_t a;
    asm("{ .reg .u64 t; cvta.to.shared.u64 t, %1; cvt.u32.u64 %0, t; }"
        : "=r"(a) : "l"(p));
    return a;
}
__device__ __forceinline__ void cp16(uint32_t dst, const void* src) {
    asm volatile("cp.async.cg.shared.global [%0], [%1], 16;"
                 :: "r"(dst), "l"(src) : "memory");
}
__device__ __forceinline__ void cp_commit() {
    asm volatile("cp.async.commit_group;" ::: "memory");
}
__device__ __forceinline__ void ldmx4(uint32_t* r, uint32_t addr) {
    asm volatile("ldmatrix.sync.aligned.m8n8.x4.shared.b16 {%0,%1,%2,%3}, [%4];"
                 : "=r"(r[0]), "=r"(r[1]), "=r"(r[2]), "=r"(r[3]) : "r"(addr));
}
__device__ __forceinline__ void mma_f16(float* d, const uint32_t* a,
                                        uint32_t b0, uint32_t b1) {
    asm volatile(
        "mma.sync.aligned.m16n8k16.row.col.f32.f16.f16.f32 "
        "{%0,%1,%2,%3}, {%4,%5,%6,%7}, {%8,%9}, {%0,%1,%2,%3};"
        : "+f"(d[0]), "+f"(d[1]), "+f"(d[2]), "+f"(d[3])
        : "r"(a[0]), "r"(a[1]), "r"(a[2]), "r"(a[3]), "r"(b0), "r"(b1));
}

// ---------------------------------------------------------------------------
__global__ void k_style(const float* __restrict__ style, const float* __restrict__ mw,
                        const float* __restrict__ mb) {
    int b = blockIdx.x, i = threadIdx.x;
    __shared__ float st[SD];
    st[i] = style[b * SD + i];
    __syncthreads();
    const float* row = mw + (size_t)i * SD;
    float acc = 0.f;
#pragma unroll 4
    for (int j = 0; j < SD; j += 4) {
        float4 m = *(const float4*)(row + j);
        acc += m.x * st[j] + m.y * st[j + 1] + m.z * st[j + 2] + m.w * st[j + 3];
    }
    g_s[b * CI + i] = acc * 0.04419417382415922f + mb[i];
}

__global__ void k_w2(const float* __restrict__ cw) {
    int tid = blockIdx.x * blockDim.x + threadIdx.x;
    if (tid >= CO * CI) return;
    const float* p = cw + (size_t)tid * 9;
    float a = 0.f;
#pragma unroll
    for (int k = 0; k < 9; ++k) a += p[k] * p[k];
    g_W2[tid] = a;
}

__global__ void k_alpha() {
    int b = blockIdx.x, o = threadIdx.x;
    __shared__ float s2[CI];
    float sv = g_s[b * CI + o];
    s2[o] = sv * sv;
    __syncthreads();
    const float* row = g_W2 + (size_t)o * CI;
    float acc = 0.f;
#pragma unroll 4
    for (int j = 0; j < CI; j += 4) {
        float4 m = *(const float4*)(row + j);
        acc += m.x * s2[j] + m.y * s2[j + 1] + m.z * s2[j + 2] + m.w * s2[j + 3];
    }
    const float wscale2 = 1.0f / 4608.0f;
    g_alpha[b * CO + o] = 0.014731391274719739f * rsqrtf(wscale2 * acc + 1e-8f);
}

// g_x[b,y,q,i] = fp16(x[b,i,y,q] * s[b,i])  — paired-i uint stores
__global__ void k_xsplit(const float* __restrict__ x) {
    int by = blockIdx.x;
    int b = by >> 5, y = by & 31;
    int t = threadIdx.x;   // 128 threads
    unsigned* px = (unsigned*)g_x;
#pragma unroll 1
    for (int c = 0; c < 2; ++c) {
        int ipair = c * 128 + t;             // 0..255
        int i = ipair * 2;
        const float* s0 = x + ((size_t)(b * CI + i) * 32 + y) * 32;
        const float* s1 = s0 + 1024;
        float sv0 = g_s[b * CI + i], sv1 = g_s[b * CI + i + 1];
        unsigned pk[32];
#pragma unroll
        for (int q4 = 0; q4 < 8; ++q4) {
            float4 f0 = *(const float4*)(s0 + q4 * 4);
            float4 f1 = *(const float4*)(s1 + q4 * 4);
            pk[q4 * 4 + 0] = h2u(__floats2half2_rn(f0.x * sv0, f1.x * sv1));
            pk[q4 * 4 + 1] = h2u(__floats2half2_rn(f0.y * sv0, f1.y * sv1));
            pk[q4 * 4 + 2] = h2u(__floats2half2_rn(f0.z * sv0, f1.z * sv1));
            pk[q4 * 4 + 3] = h2u(__floats2half2_rn(f0.w * sv0, f1.w * sv1));
        }
        size_t rowbase = (size_t)(b * 32 + y) * 32 * (CI / 2) + (size_t)ipair;
#pragma unroll
        for (int q = 0; q < 32; ++q)
            px[rowbase + (size_t)q * (CI / 2)] = pk[q];
    }
}

// raw taps -> fp16, layout [tap][o][i] — paired-i uint stores
__global__ void k_wsplit(const float* __restrict__ cw) {
    int tid = blockIdx.x * blockDim.x + threadIdx.x;
    if (tid >= CO * CI / 2) return;
    int o = tid >> 8, ipair = tid & 255;
    int i = ipair * 2;
    const float* p0 = cw + ((size_t)o * CI + i) * 9;
    const float* p1 = p0 + 9;
    unsigned* pk = (unsigned*)g_k;
#pragma unroll
    for (int k = 0; k < 9; ++k) {
        unsigned v = h2u(__floats2half2_rn(p0[k], p1[k]));
        pk[((size_t)k * CO + o) * (CI / 2) + ipair] = v;
    }
}

// ---------------------------------------------------------------------------
// z GEMM: z[b,o,tap,sp] = sum_i w[tap,o,i] * xm[b,i,sp]   (fp16, fp32 accum)
// CTA: M=128 rows of (tap,o), N=256 spatial, K=512 in 16 stages of 32.
// 512 threads, 16 warps (4x4), warp tile 32x64. 4-stage cp.async (24KB each).
#define KSTG 16
#define STG_B 24576

__global__ void __launch_bounds__(512, 1)
k_zgemm() {
    extern __shared__ __align__(1024) char smem[];
    const uint32_t sb = smem_u32(smem);

    const int tid = threadIdx.x;
    const int wid = tid >> 5, ln = tid & 31;
    const int b = blockIdx.x >> 2;
    const int nblk = blockIdx.x & 3;
    const int row0 = blockIdx.y * 128;
    const int tp = row0 >> 9;
    const int o0 = row0 & 511;
    const int wm = wid & 3, wn = wid >> 2;
    const int g = ln >> 2, t4 = ln & 3;

    // --- cp.async: A = 1 chunk/thread, B = 2 chunks/thread ---
    const char* gA = (const char*)g_k;
    const char* gB = (const char*)g_x;
    const char* srcA;
    uint32_t dstA;
    {
        int r = tid >> 2;
        uint32_t c = (uint32_t)(tid & 3) << 4;
        srcA = gA + ((size_t)(tp * CO + o0 + r) * CI) * 2 + c;
        dstA = sb + (uint32_t)(r * 64) + (c ^ (uint32_t)((r & 6) << 3));
    }
    const char* srcB[2];
    uint32_t dstB[2];
#pragma unroll
    for (int j = 0; j < 2; ++j) {
        int id = tid + 512 * j;
        int r = id >> 2;
        uint32_t c = (uint32_t)(id & 3) << 4;
        srcB[j] = gB + ((size_t)(b * 1024 + nblk * 256 + r) * CI) * 2 + c;
        dstB[j] = sb + 8192 + (uint32_t)(r * 64) + (c ^ (uint32_t)((r & 6) << 3));
    }

    // --- ldmatrix per-lane fragment addresses ---
    uint32_t aAddr[2], bAddr[4];
#pragma unroll
    for (int mt = 0; mt < 2; ++mt) {
        int mrow = wm * 32 + mt * 16 + (ln & 15);
        uint32_t hi = (uint32_t)(ln >> 4) << 4;
        aAddr[mt] = sb + (uint32_t)(mrow * 64) + (hi ^ (uint32_t)((mrow & 6) << 3));
    }
#pragma unroll
    for (int np = 0; np < 4; ++np) {
        int nrow = wn * 64 + np * 16 + ((ln >> 4) & 1) * 8 + (ln & 7);
        uint32_t hi = (uint32_t)((ln >> 3) & 1) << 4;
        bAddr[np] = sb + 8192 + (uint32_t)(nrow * 64) + (hi ^ (uint32_t)((nrow & 6) << 3));
    }

    float acc[2][8][4];
#pragma unroll
    for (int mt = 0; mt < 2; ++mt)
#pragma unroll
        for (int nt = 0; nt < 8; ++nt)
#pragma unroll
            for (int e = 0; e < 4; ++e) acc[mt][nt][e] = 0.f;

    // --- prologue: issue stages 0..2 ---
#pragma unroll
    for (int s = 0; s < 3; ++s) {
        uint32_t so = (uint32_t)(s & 3) * STG_B;
        uint32_t go = (uint32_t)s * 64;
        cp16(dstA + so, srcA + go);
        cp16(dstB[0] + so, srcB[0] + go);
        cp16(dstB[1] + so, srcB[1] + go);
        cp_commit();
    }

#pragma unroll 1
    for (int s = 0; s < KSTG; ++s) {
        asm volatile("cp.async.wait_group 2;" ::: "memory");
        __syncthreads();

        if (s + 3 < KSTG) {
            uint32_t so = (uint32_t)((s + 3) & 3) * STG_B;
            uint32_t go = (uint32_t)(s + 3) * 64;
            cp16(dstA + so, srcA + go);
            cp16(dstB[0] + so, srcB[0] + go);
            cp16(dstB[1] + so, srcB[1] + go);
        }
        cp_commit();

        const uint32_t so = (uint32_t)(s & 3) * STG_B;
#pragma unroll
        for (int kt = 0; kt < 2; ++kt) {
            const uint32_t kx = (uint32_t)(kt << 5);
            uint32_t a[2][4];
            ldmx4(a[0], (aAddr[0] + so) ^ kx);
            ldmx4(a[1], (aAddr[1] + so) ^ kx);
#pragma unroll
            for (int np = 0; np < 4; ++np) {
                uint32_t bb[4];
                ldmx4(bb, (bAddr[np] + so) ^ kx);
                mma_f16(acc[0][2 * np],     a[0], bb[0], bb[1]);
                mma_f16(acc[0][2 * np + 1], a[0], bb[2], bb[3]);
                mma_f16(acc[1][2 * np],     a[1], bb[0], bb[1]);
                mma_f16(acc[1][2 * np + 1], a[1], bb[2], bb[3]);
            }
        }
        __syncthreads();
    }

    // --- epilogue: write z fp16 (half2 per 2 columns) ---
#pragma unroll
    for (int mt = 0; mt < 2; ++mt)
#pragma unroll
        for (int rr = 0; rr < 2; ++rr) {
            int o = o0 + wm * 32 + mt * 16 + rr * 8 + g;
            __half2* zb = (__half2*)(g_z + ((size_t)(b * CO + o) * 9 + tp) * 1024);
#pragma unroll
            for (int nt = 0; nt < 8; ++nt) {
                int nl = wn * 64 + nt * 8 + 2 * t4;
                int sp = nblk * 256 + nl;
                zb[sp >> 1] = __floats2half2_rn(acc[mt][nt][rr * 2],
                                                acc[mt][nt][rr * 2 + 1]);
            }
        }
}

// ---------------------------------------------------------------------------
// Combine: per (b,o) apply separable phase stencil + epilogue.
__global__ void __launch_bounds__(256)
k_comb(const float* __restrict__ noise, const float* __restrict__ nwp,
       const float* __restrict__ ab, float* __restrict__ out) {
    extern __shared__ float sm[];
    float* zs = sm;              // 9 * 1024
    float* us = sm + 9216;       // 3 * 32 * 64

    const int bo = blockIdx.x;
    const int b = bo >> 9, o = bo & 511;
    const int tid = threadIdx.x;

    const __half2* zp2 = (const __half2*)(g_z + (size_t)bo * 9216);
#pragma unroll 4
    for (int j = tid; j < 4608; j += 256) {
        float2 f = __half22float2(zp2[j]);
        zs[2 * j] = f.x;
        zs[2 * j + 1] = f.y;
    }
    __syncthreads();

#pragma unroll 1
    for (int j = tid; j < 6144; j += 256) {
        int X = j & 63, y = (j >> 6) & 31, ky = j >> 11;
        int rx = X & 1, q = X >> 1;
        float a = 0.f;
#pragma unroll
        for (int dx = 0; dx < 3; ++dx) {
            int qq = q - 1 + dx;
            if (qq >= 0 && qq < 32) {
#pragma unroll
                for (int kx = 0; kx < 3; ++kx)
                    a += c_M[rx][dx][kx] * zs[(ky * 3 + kx) * 1024 + y * 32 + qq];
            }
        }
        us[j] = a;
    }
    __syncthreads();

    const float alp = g_alpha[b * CO + o];
    const float bia = ab[o];
    const float nw = *nwp;
#pragma unroll 1
    for (int j = tid; j < 4096; j += 256) {
        int X = j & 63, Y = j >> 6;
        int ry = Y & 1, p = Y >> 1;
        float a = 0.f;
#pragma unroll
        for (int dy = 0; dy < 3; ++dy) {
            int pp = p - 1 + dy;
            if (pp >= 0 && pp < 32) {
#pragma unroll
                for (int ky = 0; ky < 3; ++ky)
                    a += c_M[ry][dy][ky] * us[ky * 2048 + pp * 64 + X];
            }
        }
        float v = a * alp + nw * __ldg(&noise[b * 4096 + j]) + bia;
        v = (v > 0.f ? v : 0.2f * v) * 1.4142135623730951f;
        out[(size_t)bo * 4096 + j] = v;
    }
}

// ---------------------------------------------------------------------------
extern "C" void kernel_launch(void* const* d_in, const int* in_sizes, int n_in,
                              void* d_out, int out_size) {
    const float* x           = (const float*)d_in[0];
    const float* style       = (const float*)d_in[1];
    const float* noise       = (const float*)d_in[2];
    const float* conv_weight = (const float*)d_in[3];
    const float* mod_weight  = (const float*)d_in[4];
    const float* mod_bias    = (const float*)d_in[5];
    const float* noise_w     = (const float*)d_in[6];
    const float* act_bias    = (const float*)d_in[7];
    float* out = (float*)d_out;

    cudaFuncSetAttribute(k_zgemm, cudaFuncAttributeMaxDynamicSharedMemorySize, 98304);
    cudaFuncSetAttribute(k_comb, cudaFuncAttributeMaxDynamicSharedMemorySize, 61440);

    k_style<<<NB, 512>>>(style, mod_weight, mod_bias);
    k_w2<<<512, 512>>>(conv_weight);
    k_alpha<<<NB, 512>>>();
    k_xsplit<<<NB * 32, 128>>>(x);
    k_wsplit<<<256, 512>>>(conv_weight);
    k_zgemm<<<dim3(64, 36), 512, 98304>>>();
    k_comb<<<NB * CO, 256, 61440>>>(noise, noise_w, act_bias, out);
}

// round 8
// speedup vs baseline: 1.0257x; 1.0257x over previous
#include <cuda_runtime.h>
#include <cuda_fp16.h>
#include <cstdint>
#include <math.h>

#define NB 16
#define CI 512
#define CO 512
#define SD 512

// ---------------------------------------------------------------------------
// Scratch (__device__ globals — allowed)
__device__ float g_s[NB * CI];
__device__ float g_W2[CO * CI];
__device__ float g_alpha[NB * CO];
__device__ __half g_x[(size_t)NB * 32 * 32 * CI];   // [b][y][x][i] fp16, modulated
__device__ __half g_k[(size_t)9 * CO * CI];         // [tap][o][i] fp16
__device__ __half g_z[(size_t)NB * CO * 9 * 1024];  // [b][o][tap][32x32] fp16

// (upsample-2 transposed k3) ∘ (blur [1,3,3,1]/4) composition, per parity
__constant__ float c_M[2][3][3] = {
    {{0.00f, 0.25f, 0.75f}, {0.75f, 0.75f, 0.25f}, {0.25f, 0.00f, 0.00f}},
    {{0.00f, 0.00f, 0.25f}, {0.25f, 0.75f, 0.75f}, {0.75f, 0.25f, 0.00f}}
};

// ---------------------------------------------------------------------------
__device__ __forceinline__ unsigned h2u(__half2 h) {
    return *reinterpret_cast<unsigned*>(&h);
}
__device__ __forceinline__ uint32_t smem_u32(const void* p) {
    uint32_t a;
    asm("{ .reg .u64 t; cvta.to.shared.u64 t, %1; cvt.u32.u64 %0, t; }"
        : "=r"(a) : "l"(p));
    return a;
}
__device__ __forceinline__ void cp16(uint32_t dst, const void* src) {
    asm volatile("cp.async.cg.shared.global [%0], [%1], 16;"
                 :: "r"(dst), "l"(src) : "memory");
}
__device__ __forceinline__ void cp_commit() {
    asm volatile("cp.async.commit_group;" ::: "memory");
}
__device__ __forceinline__ void ldmx4(uint32_t* r, uint32_t addr) {
    asm volatile("ldmatrix.sync.aligned.m8n8.x4.shared.b16 {%0,%1,%2,%3}, [%4];"
                 : "=r"(r[0]), "=r"(r[1]), "=r"(r[2]), "=r"(r[3]) : "r"(addr));
}
__device__ __forceinline__ void mma_f16(float* d, const uint32_t* a,
                                        uint32_t b0, uint32_t b1) {
    asm volatile(
        "mma.sync.aligned.m16n8k16.row.col.f32.f16.f16.f32 "
        "{%0,%1,%2,%3}, {%4,%5,%6,%7}, {%8,%9}, {%0,%1,%2,%3};"
        : "+f"(d[0]), "+f"(d[1]), "+f"(d[2]), "+f"(d[3])
        : "r"(a[0]), "r"(a[1]), "r"(a[2]), "r"(a[3]), "r"(b0), "r"(b1));
}

// ---------------------------------------------------------------------------
__global__ void k_style(const float* __restrict__ style, const float* __restrict__ mw,
                        const float* __restrict__ mb) {
    int b = blockIdx.x, i = threadIdx.x;
    __shared__ float st[SD];
    st[i] = style[b * SD + i];
    __syncthreads();
    const float* row = mw + (size_t)i * SD;
    float acc = 0.f;
#pragma unroll 4
    for (int j = 0; j < SD; j += 4) {
        float4 m = *(const float4*)(row + j);
        acc += m.x * st[j] + m.y * st[j + 1] + m.z * st[j + 2] + m.w * st[j + 3];
    }
    g_s[b * CI + i] = acc * 0.04419417382415922f + mb[i];
}

__global__ void k_w2(const float* __restrict__ cw) {
    int tid = blockIdx.x * blockDim.x + threadIdx.x;
    if (tid >= CO * CI) return;
    const float* p = cw + (size_t)tid * 9;
    float a = 0.f;
#pragma unroll
    for (int k = 0; k < 9; ++k) a += p[k] * p[k];
    g_W2[tid] = a;
}

__global__ void k_alpha() {
    int b = blockIdx.x, o = threadIdx.x;
    __shared__ float s2[CI];
    float sv = g_s[b * CI + o];
    s2[o] = sv * sv;
    __syncthreads();
    const float* row = g_W2 + (size_t)o * CI;
    float acc = 0.f;
#pragma unroll 4
    for (int j = 0; j < CI; j += 4) {
        float4 m = *(const float4*)(row + j);
        acc += m.x * s2[j] + m.y * s2[j + 1] + m.z * s2[j + 2] + m.w * s2[j + 3];
    }
    const float wscale2 = 1.0f / 4608.0f;
    g_alpha[b * CO + o] = 0.014731391274719739f * rsqrtf(wscale2 * acc + 1e-8f);
}

// g_x[b,y,q,i] = fp16(x[b,i,y,q] * s[b,i])  — paired-i uint stores
__global__ void k_xsplit(const float* __restrict__ x) {
    int by = blockIdx.x;
    int b = by >> 5, y = by & 31;
    int t = threadIdx.x;   // 128 threads
    unsigned* px = (unsigned*)g_x;
#pragma unroll 1
    for (int c = 0; c < 2; ++c) {
        int ipair = c * 128 + t;             // 0..255
        int i = ipair * 2;
        const float* s0 = x + ((size_t)(b * CI + i) * 32 + y) * 32;
        const float* s1 = s0 + 1024;
        float sv0 = g_s[b * CI + i], sv1 = g_s[b * CI + i + 1];
        unsigned pk[32];
#pragma unroll
        for (int q4 = 0; q4 < 8; ++q4) {
            float4 f0 = *(const float4*)(s0 + q4 * 4);
            float4 f1 = *(const float4*)(s1 + q4 * 4);
            pk[q4 * 4 + 0] = h2u(__floats2half2_rn(f0.x * sv0, f1.x * sv1));
            pk[q4 * 4 + 1] = h2u(__floats2half2_rn(f0.y * sv0, f1.y * sv1));
            pk[q4 * 4 + 2] = h2u(__floats2half2_rn(f0.z * sv0, f1.z * sv1));
            pk[q4 * 4 + 3] = h2u(__floats2half2_rn(f0.w * sv0, f1.w * sv1));
        }
        size_t rowbase = (size_t)(b * 32 + y) * 32 * (CI / 2) + (size_t)ipair;
#pragma unroll
        for (int q = 0; q < 32; ++q)
            px[rowbase + (size_t)q * (CI / 2)] = pk[q];
    }
}

// raw taps -> fp16, layout [tap][o][i] — paired-i uint stores
__global__ void k_wsplit(const float* __restrict__ cw) {
    int tid = blockIdx.x * blockDim.x + threadIdx.x;
    if (tid >= CO * CI / 2) return;
    int o = tid >> 8, ipair = tid & 255;
    int i = ipair * 2;
    const float* p0 = cw + ((size_t)o * CI + i) * 9;
    const float* p1 = p0 + 9;
    unsigned* pk = (unsigned*)g_k;
#pragma unroll
    for (int k = 0; k < 9; ++k) {
        unsigned v = h2u(__floats2half2_rn(p0[k], p1[k]));
        pk[((size_t)k * CO + o) * (CI / 2) + ipair] = v;
    }
}

// ---------------------------------------------------------------------------
// Persistent z GEMM: 144 CTAs (36 row-tiles x 4 b-groups), A resident in smem.
// CTA: M=128 (tap,o), per-CTA loop over 16 n-tiles of 256; K=512, 16 stages.
// smem: A[16 kchunks][128 rows][64B] = 128KB, B 2 x 16KB double buffer.
#define A_BYTES 131072
#define B_STG 16384

__global__ void __launch_bounds__(256, 1)
k_zgemm() {
    extern __shared__ __align__(1024) char smem[];
    const uint32_t sb = smem_u32(smem);
    const uint32_t bbase = sb + A_BYTES;

    const int tid = threadIdx.x;
    const int wid = tid >> 5, ln = tid & 31;
    const int rt = blockIdx.x % 36;
    const int bg = blockIdx.x / 36;     // 0..3, each owns 4 b's
    const int tp = rt >> 2;
    const int o0 = (rt & 3) * 128;
    const int wm = wid & 1, wn = wid >> 1;
    const int g = ln >> 2, t4 = ln & 3;

    const char* gA = (const char*)g_k;
    const char* gB = (const char*)g_x;

    // --- load full A (128 x 512 fp16, 16 kchunks of 8KB) ---
    {
        int r = tid >> 2;
        uint32_t c = (uint32_t)(tid & 3) << 4;
        uint32_t sw = c ^ (uint32_t)((r & 6) << 3);
        const char* sA = gA + ((size_t)(tp * CO + o0 + r) * CI) * 2 + c;
        const char* sA2 = gA + ((size_t)(tp * CO + o0 + r + 64) * CI) * 2 + c;
        uint32_t dA = sb + (uint32_t)(r * 64) + sw;
        int r2 = r + 64;
        uint32_t dA2 = sb + (uint32_t)(r2 * 64) + (c ^ (uint32_t)((r2 & 6) << 3));
#pragma unroll
        for (int kc = 0; kc < 16; ++kc) {
            cp16(dA + kc * 8192, sA + kc * 64);
            cp16(dA2 + kc * 8192, sA2 + kc * 64);
        }
        cp_commit();
    }

    // --- B stage load setup: 4 chunks of 16B per thread per stage ---
    int brow[4];
    uint32_t bco[4], bdst[4];
#pragma unroll
    for (int j = 0; j < 4; ++j) {
        int id = tid + 256 * j;
        brow[j] = id >> 2;                       // 0..255 within n-tile
        bco[j] = (uint32_t)(id & 3) << 4;
        bdst[j] = bbase + (uint32_t)(brow[j] * 64) +
                  (bco[j] ^ (uint32_t)((brow[j] & 6) << 3));
    }

    // --- ldmatrix fragment addresses (A: 64 M rows, B: 64 N rows per warp) ---
    uint32_t aAddr[4], bAddr[4];
#pragma unroll
    for (int mt = 0; mt < 4; ++mt) {
        int mrow = wm * 64 + mt * 16 + (ln & 15);
        uint32_t hi = (uint32_t)(ln >> 4) << 4;
        aAddr[mt] = sb + (uint32_t)(mrow * 64) + (hi ^ (uint32_t)((mrow & 6) << 3));
    }
#pragma unroll
    for (int np = 0; np < 4; ++np) {
        int nrow = wn * 64 + np * 16 + ((ln >> 4) & 1) * 8 + (ln & 7);
        uint32_t hi = (uint32_t)((ln >> 3) & 1) << 4;
        bAddr[np] = bbase + (uint32_t)(nrow * 64) + (hi ^ (uint32_t)((nrow & 6) << 3));
    }

    float acc[4][8][4];
#pragma unroll
    for (int mt = 0; mt < 4; ++mt)
#pragma unroll
        for (int nt = 0; nt < 8; ++nt)
#pragma unroll
            for (int e = 0; e < 4; ++e) acc[mt][nt][e] = 0.f;

    // --- prologue: B stage g=0 ---
    {
        int b = bg * 4, nblk = 0;
#pragma unroll
        for (int j = 0; j < 4; ++j)
            cp16(bdst[j], gB + ((size_t)(b * 1024 + nblk * 256 + brow[j]) * CI) * 2 + bco[j]);
        cp_commit();
    }

#pragma unroll 1
    for (int gs = 0; gs < 256; ++gs) {
        // issue B stage gs+1 (slot (gs+1)&1); compute gs-1 finished at prior sync
        if (gs + 1 < 256) {
            int g1 = gs + 1;
            int nt1 = g1 >> 4, ks1 = g1 & 15;
            int b1 = bg * 4 + (nt1 >> 2), nb1 = nt1 & 3;
            uint32_t so = (uint32_t)((g1 & 1) ? B_STG : 0);
            size_t base = ((size_t)(b1 * 1024 + nb1 * 256) * CI + ks1 * 32) * 2;
#pragma unroll
            for (int j = 0; j < 4; ++j)
                cp16(bdst[j] + so, gB + base + (size_t)brow[j] * CI * 2 + bco[j]);
        }
        cp_commit();
        asm volatile("cp.async.wait_group 1;" ::: "memory");
        __syncthreads();

        const int ks = gs & 15;
        const uint32_t aOff = (uint32_t)(ks * 8192);
        const uint32_t bOff = (uint32_t)((gs & 1) ? B_STG : 0);
#pragma unroll
        for (int kt = 0; kt < 2; ++kt) {
            const uint32_t kx = (uint32_t)(kt << 5);
            uint32_t a[4][4];
#pragma unroll
            for (int mt = 0; mt < 4; ++mt)
                ldmx4(a[mt], (aAddr[mt] + aOff) ^ kx);
#pragma unroll
            for (int np = 0; np < 4; ++np) {
                uint32_t bb[4];
                ldmx4(bb, (bAddr[np] + bOff) ^ kx);
#pragma unroll
                for (int mt = 0; mt < 4; ++mt) {
                    mma_f16(acc[mt][2 * np],     a[mt], bb[0], bb[1]);
                    mma_f16(acc[mt][2 * np + 1], a[mt], bb[2], bb[3]);
                }
            }
        }

        if (ks == 15) {
            // epilogue for n-tile nt: write z fp16, reset accums
            int nt = gs >> 4;
            int b = bg * 4 + (nt >> 2), nblk = nt & 3;
#pragma unroll
            for (int mt = 0; mt < 4; ++mt)
#pragma unroll
                for (int rr = 0; rr < 2; ++rr) {
                    int o = o0 + wm * 64 + mt * 16 + rr * 8 + g;
                    __half2* zb = (__half2*)(g_z + ((size_t)(b * CO + o) * 9 + tp) * 1024);
#pragma unroll
                    for (int nt8 = 0; nt8 < 8; ++nt8) {
                        int nl = wn * 64 + nt8 * 8 + 2 * t4;
                        int sp = nblk * 256 + nl;
                        zb[sp >> 1] = __floats2half2_rn(acc[mt][nt8][rr * 2],
                                                        acc[mt][nt8][rr * 2 + 1]);
                    }
                }
#pragma unroll
            for (int mt = 0; mt < 4; ++mt)
#pragma unroll
                for (int nt8 = 0; nt8 < 8; ++nt8)
#pragma unroll
                    for (int e = 0; e < 4; ++e) acc[mt][nt8][e] = 0.f;
        }
        __syncthreads();
    }
}

// ---------------------------------------------------------------------------
// Combine: per (b,o) apply separable phase stencil + epilogue.
__global__ void __launch_bounds__(256)
k_comb(const float* __restrict__ noise, const float* __restrict__ nwp,
       const float* __restrict__ ab, float* __restrict__ out) {
    extern __shared__ float sm[];
    float* zs = sm;              // 9 * 1024
    float* us = sm + 9216;       // 3 * 32 * 64

    const int bo = blockIdx.x;
    const int b = bo >> 9, o = bo & 511;
    const int tid = threadIdx.x;

    const __half2* zp2 = (const __half2*)(g_z + (size_t)bo * 9216);
#pragma unroll 4
    for (int j = tid; j < 4608; j += 256) {
        float2 f = __half22float2(zp2[j]);
        zs[2 * j] = f.x;
        zs[2 * j + 1] = f.y;
    }
    __syncthreads();

#pragma unroll 1
    for (int j = tid; j < 6144; j += 256) {
        int X = j & 63, y = (j >> 6) & 31, ky = j >> 11;
        int rx = X & 1, q = X >> 1;
        float a = 0.f;
#pragma unroll
        for (int dx = 0; dx < 3; ++dx) {
            int qq = q - 1 + dx;
            if (qq >= 0 && qq < 32) {
#pragma unroll
                for (int kx = 0; kx < 3; ++kx)
                    a += c_M[rx][dx][kx] * zs[(ky * 3 + kx) * 1024 + y * 32 + qq];
            }
        }
        us[j] = a;
    }
    __syncthreads();

    const float alp = g_alpha[b * CO + o];
    const float bia = ab[o];
    const float nw = *nwp;
#pragma unroll 1
    for (int j = tid; j < 4096; j += 256) {
        int X = j & 63, Y = j >> 6;
        int ry = Y & 1, p = Y >> 1;
        float a = 0.f;
#pragma unroll
        for (int dy = 0; dy < 3; ++dy) {
            int pp = p - 1 + dy;
            if (pp >= 0 && pp < 32) {
#pragma unroll
                for (int ky = 0; ky < 3; ++ky)
                    a += c_M[ry][dy][ky] * us[ky * 2048 + pp * 64 + X];
            }
        }
        float v = a * alp + nw * __ldg(&noise[b * 4096 + j]) + bia;
        v = (v > 0.f ? v : 0.2f * v) * 1.4142135623730951f;
        out[(size_t)bo * 4096 + j] = v;
    }
}

// ---------------------------------------------------------------------------
extern "C" void kernel_launch(void* const* d_in, const int* in_sizes, int n_in,
                              void* d_out, int out_size) {
    const float* x           = (const float*)d_in[0];
    const float* style       = (const float*)d_in[1];
    const float* noise       = (const float*)d_in[2];
    const float* conv_weight = (const float*)d_in[3];
    const float* mod_weight  = (const float*)d_in[4];
    const float* mod_bias    = (const float*)d_in[5];
    const float* noise_w     = (const float*)d_in[6];
    const float* act_bias    = (const float*)d_in[7];
    float* out = (float*)d_out;

    cudaFuncSetAttribute(k_zgemm, cudaFuncAttributeMaxDynamicSharedMemorySize,
                         A_BYTES + 2 * B_STG);
    cudaFuncSetAttribute(k_comb, cudaFuncAttributeMaxDynamicSharedMemorySize, 61440);

    // Order chosen so k_zgemm lands in the ncu capture window (local index 3).
    k_style<<<NB, 512>>>(style, mod_weight, mod_bias);
    k_xsplit<<<NB * 32, 128>>>(x);
    k_wsplit<<<256, 512>>>(conv_weight);
    k_zgemm<<<144, 256, A_BYTES + 2 * B_STG>>>();
    k_w2<<<512, 512>>>(conv_weight);
    k_alpha<<<NB, 512>>>();
    k_comb<<<NB * CO, 256, 61440>>>(noise, noise_w, act_bias, out);
}

// round 9
// speedup vs baseline: 1.0923x; 1.0649x over previous
#include <cuda_runtime.h>
#include <cuda_fp16.h>
#include <cstdint>
#include <math.h>

#define NB 16
#define CI 512
#define CO 512
#define SD 512

// ---------------------------------------------------------------------------
// Scratch (__device__ globals — allowed)
__device__ float g_s[NB * CI];
__device__ float g_W2[CO * CI];
__device__ __half g_x[(size_t)NB * 32 * 32 * CI];   // [b][y][x][i] fp16, modulated
__device__ __half g_k[(size_t)9 * CO * CI];         // [tap][o][i] fp16
__device__ __half g_z[(size_t)NB * CO * 9 * 1024];  // [b][o][tap][32x32] fp16

// (upsample-2 transposed k3) ∘ (blur [1,3,3,1]/4) composition, per parity
__constant__ float c_M[2][3][3] = {
    {{0.00f, 0.25f, 0.75f}, {0.75f, 0.75f, 0.25f}, {0.25f, 0.00f, 0.00f}},
    {{0.00f, 0.00f, 0.25f}, {0.25f, 0.75f, 0.75f}, {0.75f, 0.25f, 0.00f}}
};

// ---------------------------------------------------------------------------
__device__ __forceinline__ unsigned h2u(__half2 h) {
    return *reinterpret_cast<unsigned*>(&h);
}
__device__ __forceinline__ uint32_t smem_u32(const void* p) {
    uint32_t a;
    asm("{ .reg .u64 t; cvta.to.shared.u64 t, %1; cvt.u32.u64 %0, t; }"
        : "=r"(a) : "l"(p));
    return a;
}
__device__ __forceinline__ void cp16(uint32_t dst, const void* src) {
    asm volatile("cp.async.cg.shared.global [%0], [%1], 16;"
                 :: "r"(dst), "l"(src) : "memory");
}
__device__ __forceinline__ void cp_commit() {
    asm volatile("cp.async.commit_group;" ::: "memory");
}
__device__ __forceinline__ void ldmx4(uint32_t* r, uint32_t addr) {
    asm volatile("ldmatrix.sync.aligned.m8n8.x4.shared.b16 {%0,%1,%2,%3}, [%4];"
                 : "=r"(r[0]), "=r"(r[1]), "=r"(r[2]), "=r"(r[3]) : "r"(addr));
}
__device__ __forceinline__ void mma_f16(float* d, const uint32_t* a,
                                        uint32_t b0, uint32_t b1) {
    asm volatile(
        "mma.sync.aligned.m16n8k16.row.col.f32.f16.f16.f32 "
        "{%0,%1,%2,%3}, {%4,%5,%6,%7}, {%8,%9}, {%0,%1,%2,%3};"
        : "+f"(d[0]), "+f"(d[1]), "+f"(d[2]), "+f"(d[3])
        : "r"(a[0]), "r"(a[1]), "r"(a[2]), "r"(a[3]), "r"(b0), "r"(b1));
}

// ---------------------------------------------------------------------------
__global__ void k_style(const float* __restrict__ style, const float* __restrict__ mw,
                        const float* __restrict__ mb) {
    int b = blockIdx.x, i = threadIdx.x;
    __shared__ float st[SD];
    st[i] = style[b * SD + i];
    __syncthreads();
    const float* row = mw + (size_t)i * SD;
    float acc = 0.f;
#pragma unroll 4
    for (int j = 0; j < SD; j += 4) {
        float4 m = *(const float4*)(row + j);
        acc += m.x * st[j] + m.y * st[j + 1] + m.z * st[j + 2] + m.w * st[j + 3];
    }
    g_s[b * CI + i] = acc * 0.04419417382415922f + mb[i];
}

// Fused prep: wsplit (bid<256) | w2 (256..767) | xsplit (768..1023)
__global__ void __launch_bounds__(512)
k_prep(const float* __restrict__ cw, const float* __restrict__ x) {
    int bid = blockIdx.x, tid = threadIdx.x;
    if (bid < 256) {
        // wsplit: raw taps -> fp16 [tap][o][i], paired-i stores
        int idx = bid * 512 + tid;
        int o = idx >> 8, ipair = idx & 255;
        int i = ipair * 2;
        const float* p0 = cw + ((size_t)o * CI + i) * 9;
        const float* p1 = p0 + 9;
        unsigned* pk = (unsigned*)g_k;
#pragma unroll
        for (int k = 0; k < 9; ++k) {
            unsigned v = h2u(__floats2half2_rn(p0[k], p1[k]));
            pk[((size_t)k * CO + o) * (CI / 2) + ipair] = v;
        }
    } else if (bid < 768) {
        // w2
        int idx = (bid - 256) * 512 + tid;
        const float* p = cw + (size_t)idx * 9;
        float a = 0.f;
#pragma unroll
        for (int k = 0; k < 9; ++k) a += p[k] * p[k];
        g_W2[idx] = a;
    } else {
        // xsplit: g_x[b,y,q,i] = fp16(x[b,i,y,q] * s[b,i])
        int xb = bid - 768;                  // 0..255
        int b = xb >> 4;
        int y = (xb & 15) * 2 + (tid >> 8);
        int ipair = tid & 255;
        int i = ipair * 2;
        const float* s0 = x + ((size_t)(b * CI + i) * 32 + y) * 32;
        const float* s1 = s0 + 1024;
        float sv0 = g_s[b * CI + i], sv1 = g_s[b * CI + i + 1];
        unsigned pk[32];
#pragma unroll
        for (int q4 = 0; q4 < 8; ++q4) {
            float4 f0 = *(const float4*)(s0 + q4 * 4);
            float4 f1 = *(const float4*)(s1 + q4 * 4);
            pk[q4 * 4 + 0] = h2u(__floats2half2_rn(f0.x * sv0, f1.x * sv1));
            pk[q4 * 4 + 1] = h2u(__floats2half2_rn(f0.y * sv0, f1.y * sv1));
            pk[q4 * 4 + 2] = h2u(__floats2half2_rn(f0.z * sv0, f1.z * sv1));
            pk[q4 * 4 + 3] = h2u(__floats2half2_rn(f0.w * sv0, f1.w * sv1));
        }
        unsigned* px = (unsigned*)g_x;
        size_t rowbase = (size_t)(b * 32 + y) * 32 * (CI / 2) + (size_t)ipair;
#pragma unroll
        for (int q = 0; q < 32; ++q)
            px[rowbase + (size_t)q * (CI / 2)] = pk[q];
    }
}

// ---------------------------------------------------------------------------
// Persistent z GEMM: 144 CTAs (36 row-tiles x 4 b-groups), A resident (128KB),
// B 4-deep ring (4x16KB). 512 threads / 16 warps, warp tile 32x64.
// One __syncthreads per stage.
#define A_BYTES 131072
#define B_STG 16384

__global__ void __launch_bounds__(512, 1)
k_zgemm() {
    extern __shared__ __align__(1024) char smem[];
    const uint32_t sb = smem_u32(smem);
    const uint32_t bbase = sb + A_BYTES;

    const int tid = threadIdx.x;
    const int wid = tid >> 5, ln = tid & 31;
    const int rt = blockIdx.x % 36;
    const int bg = blockIdx.x / 36;     // 0..3, each owns 4 b's
    const int tp = rt >> 2;
    const int o0 = (rt & 3) * 128;
    const int wm = wid & 3, wn = wid >> 2;
    const int g = ln >> 2, t4 = ln & 3;

    const char* gA = (const char*)g_k;
    const char* gB = (const char*)g_x;

    // --- load full A (128 x 512 fp16 = 128KB, 16 kchunks of 8KB) ---
    {
        int r = tid >> 2;                        // 0..127
        uint32_t c = (uint32_t)(tid & 3) << 4;
        uint32_t sw = c ^ (uint32_t)((r & 6) << 3);
        const char* sA = gA + ((size_t)(tp * CO + o0 + r) * CI) * 2 + c;
        uint32_t dA = sb + (uint32_t)(r * 64) + sw;
#pragma unroll
        for (int kc = 0; kc < 16; ++kc)
            cp16(dA + kc * 8192, sA + kc * 64);
        cp_commit();
    }

    // --- B stage setup: 2 chunks of 16B per thread per stage ---
    int brow[2];
    uint32_t bco[2], bdst[2];
#pragma unroll
    for (int j = 0; j < 2; ++j) {
        int id = tid + 512 * j;
        brow[j] = id >> 2;                       // 0..255
        bco[j] = (uint32_t)(id & 3) << 4;
        bdst[j] = bbase + (uint32_t)(brow[j] * 64) +
                  (bco[j] ^ (uint32_t)((brow[j] & 6) << 3));
    }

    // --- ldmatrix fragment addresses ---
    uint32_t aAddr[2], bAddr[4];
#pragma unroll
    for (int mt = 0; mt < 2; ++mt) {
        int mrow = wm * 32 + mt * 16 + (ln & 15);
        uint32_t hi = (uint32_t)(ln >> 4) << 4;
        aAddr[mt] = sb + (uint32_t)(mrow * 64) + (hi ^ (uint32_t)((mrow & 6) << 3));
    }
#pragma unroll
    for (int np = 0; np < 4; ++np) {
        int nrow = wn * 64 + np * 16 + ((ln >> 4) & 1) * 8 + (ln & 7);
        uint32_t hi = (uint32_t)((ln >> 3) & 1) << 4;
        bAddr[np] = bbase + (uint32_t)(nrow * 64) + (hi ^ (uint32_t)((nrow & 6) << 3));
    }

    float acc[2][8][4];
#pragma unroll
    for (int mt = 0; mt < 2; ++mt)
#pragma unroll
        for (int nt = 0; nt < 8; ++nt)
#pragma unroll
            for (int e = 0; e < 4; ++e) acc[mt][nt][e] = 0.f;

    // --- prologue: B stages 0..2 ---
#pragma unroll
    for (int s = 0; s < 3; ++s) {
        int nt1 = s >> 4, ks1 = s & 15;
        int b1 = bg * 4 + (nt1 >> 2), nb1 = nt1 & 3;
        uint32_t so = (uint32_t)(s & 3) * B_STG;
        size_t base = ((size_t)(b1 * 1024 + nb1 * 256) * CI + ks1 * 32) * 2;
        cp16(bdst[0] + so, gB + base + (size_t)brow[0] * CI * 2 + bco[0]);
        cp16(bdst[1] + so, gB + base + (size_t)brow[1] * CI * 2 + bco[1]);
        cp_commit();
    }

#pragma unroll 1
    for (int gs = 0; gs < 256; ++gs) {
        asm volatile("cp.async.wait_group 2;" ::: "memory");
        __syncthreads();   // all warps done with stage gs-1; B_gs (+A) visible

        // issue stage gs+3 into slot (gs+3)&3 == (gs-1)&3 (WAR-safe after sync)
        if (gs + 3 < 256) {
            int g1 = gs + 3;
            int nt1 = g1 >> 4, ks1 = g1 & 15;
            int b1 = bg * 4 + (nt1 >> 2), nb1 = nt1 & 3;
            uint32_t so = (uint32_t)(g1 & 3) * B_STG;
            size_t base = ((size_t)(b1 * 1024 + nb1 * 256) * CI + ks1 * 32) * 2;
            cp16(bdst[0] + so, gB + base + (size_t)brow[0] * CI * 2 + bco[0]);
            cp16(bdst[1] + so, gB + base + (size_t)brow[1] * CI * 2 + bco[1]);
        }
        cp_commit();

        const int ks = gs & 15;
        const uint32_t aOff = (uint32_t)(ks * 8192);
        const uint32_t bOff = (uint32_t)(gs & 3) * B_STG;
#pragma unroll
        for (int kt = 0; kt < 2; ++kt) {
            const uint32_t kx = (uint32_t)(kt << 5);
            uint32_t a[2][4];
            ldmx4(a[0], (aAddr[0] + aOff) ^ kx);
            ldmx4(a[1], (aAddr[1] + aOff) ^ kx);
#pragma unroll
            for (int np = 0; np < 4; ++np) {
                uint32_t bb[4];
                ldmx4(bb, (bAddr[np] + bOff) ^ kx);
                mma_f16(acc[0][2 * np],     a[0], bb[0], bb[1]);
                mma_f16(acc[0][2 * np + 1], a[0], bb[2], bb[3]);
                mma_f16(acc[1][2 * np],     a[1], bb[0], bb[1]);
                mma_f16(acc[1][2 * np + 1], a[1], bb[2], bb[3]);
            }
        }

        if (ks == 15) {
            int nt = gs >> 4;
            int b = bg * 4 + (nt >> 2), nblk = nt & 3;
#pragma unroll
            for (int mt = 0; mt < 2; ++mt)
#pragma unroll
                for (int rr = 0; rr < 2; ++rr) {
                    int o = o0 + wm * 32 + mt * 16 + rr * 8 + g;
                    __half2* zb = (__half2*)(g_z + ((size_t)(b * CO + o) * 9 + tp) * 1024);
#pragma unroll
                    for (int nt8 = 0; nt8 < 8; ++nt8) {
                        int nl = wn * 64 + nt8 * 8 + 2 * t4;
                        int sp = nblk * 256 + nl;
                        zb[sp >> 1] = __floats2half2_rn(acc[mt][nt8][rr * 2],
                                                        acc[mt][nt8][rr * 2 + 1]);
                    }
                }
#pragma unroll
            for (int mt = 0; mt < 2; ++mt)
#pragma unroll
                for (int nt8 = 0; nt8 < 8; ++nt8)
#pragma unroll
                    for (int e = 0; e < 4; ++e) acc[mt][nt8][e] = 0.f;
        }
    }
}

// ---------------------------------------------------------------------------
// Combine (+ fused alpha): per (b,o) separable phase stencil + epilogue.
__global__ void __launch_bounds__(256)
k_comb(const float* __restrict__ noise, const float* __restrict__ nwp,
       const float* __restrict__ ab, float* __restrict__ out) {
    extern __shared__ float sm[];
    float* zs = sm;              // 9 * 1024
    float* us = sm + 9216;       // 3 * 32 * 64
    float* red = sm + 15360;     // 8

    const int bo = blockIdx.x;
    const int b = bo >> 9, o = bo & 511;
    const int tid = threadIdx.x;

    // fused alpha: sum_i s^2 * W2
    {
        float part = 0.f;
        const float* wrow = g_W2 + (size_t)o * CI;
        const float* srow = g_s + b * CI;
#pragma unroll
        for (int j = tid; j < CI; j += 256) {
            float sv = srow[j];
            part += sv * sv * wrow[j];
        }
#pragma unroll
        for (int off = 16; off; off >>= 1)
            part += __shfl_xor_sync(0xFFFFFFFFu, part, off);
        if ((tid & 31) == 0) red[tid >> 5] = part;
    }

    const __half2* zp2 = (const __half2*)(g_z + (size_t)bo * 9216);
#pragma unroll 4
    for (int j = tid; j < 4608; j += 256) {
        float2 f = __half22float2(zp2[j]);
        zs[2 * j] = f.x;
        zs[2 * j + 1] = f.y;
    }
    __syncthreads();

    float asum = red[0] + red[1] + red[2] + red[3] +
                 red[4] + red[5] + red[6] + red[7];
    const float wscale2 = 1.0f / 4608.0f;
    const float alp = 0.014731391274719739f * rsqrtf(wscale2 * asum + 1e-8f);

#pragma unroll 1
    for (int j = tid; j < 6144; j += 256) {
        int X = j & 63, y = (j >> 6) & 31, ky = j >> 11;
        int rx = X & 1, q = X >> 1;
        float a = 0.f;
#pragma unroll
        for (int dx = 0; dx < 3; ++dx) {
            int qq = q - 1 + dx;
            if (qq >= 0 && qq < 32) {
#pragma unroll
                for (int kx = 0; kx < 3; ++kx)
                    a += c_M[rx][dx][kx] * zs[(ky * 3 + kx) * 1024 + y * 32 + qq];
            }
        }
        us[j] = a;
    }
    __syncthreads();

    const float bia = ab[o];
    const float nw = *nwp;
#pragma unroll 1
    for (int j = tid; j < 4096; j += 256) {
        int X = j & 63, Y = j >> 6;
        int ry = Y & 1, p = Y >> 1;
        float a = 0.f;
#pragma unroll
        for (int dy = 0; dy < 3; ++dy) {
            int pp = p - 1 + dy;
            if (pp >= 0 && pp < 32) {
#pragma unroll
                for (int ky = 0; ky < 3; ++ky)
                    a += c_M[ry][dy][ky] * us[ky * 2048 + pp * 64 + X];
            }
        }
        float v = a * alp + nw * __ldg(&noise[b * 4096 + j]) + bia;
        v = (v > 0.f ? v : 0.2f * v) * 1.4142135623730951f;
        out[(size_t)bo * 4096 + j] = v;
    }
}

// ---------------------------------------------------------------------------
extern "C" void kernel_launch(void* const* d_in, const int* in_sizes, int n_in,
                              void* d_out, int out_size) {
    const float* x           = (const float*)d_in[0];
    const float* style       = (const float*)d_in[1];
    const float* noise       = (const float*)d_in[2];
    const float* conv_weight = (const float*)d_in[3];
    const float* mod_weight  = (const float*)d_in[4];
    const float* mod_bias    = (const float*)d_in[5];
    const float* noise_w     = (const float*)d_in[6];
    const float* act_bias    = (const float*)d_in[7];
    float* out = (float*)d_out;

    cudaFuncSetAttribute(k_zgemm, cudaFuncAttributeMaxDynamicSharedMemorySize,
                         A_BYTES + 4 * B_STG);
    cudaFuncSetAttribute(k_comb, cudaFuncAttributeMaxDynamicSharedMemorySize, 61472);

    // 4 launches; k_comb is launch index 3 -> lands in the ncu capture window.
    k_style<<<NB, 512>>>(style, mod_weight, mod_bias);
    k_prep<<<1024, 512>>>(conv_weight, x);
    k_zgemm<<<144, 512, A_BYTES + 4 * B_STG>>>();
    k_comb<<<NB * CO, 256, 61472>>>(noise, noise_w, act_bias, out);
}

// round 11
// speedup vs baseline: 1.5211x; 1.3926x over previous
#include <cuda_runtime.h>
#include <cuda_fp16.h>
#include <cstdint>
#include <math.h>

#define NB 16
#define CI 512
#define CO 512
#define SD 512

// ---------------------------------------------------------------------------
// Scratch (__device__ globals — allowed)
__device__ float g_s[NB * CI];
__device__ float g_W2[CO * CI];
__device__ __half g_x[(size_t)NB * 32 * 32 * CI];   // [b][y][x][i] fp16, modulated
__device__ __half g_k[(size_t)9 * CO * CI];         // [tap][o][i] fp16
__device__ __half g_z[(size_t)NB * CO * 9 * 1024];  // [b][o][tap][32x32] fp16

// ---------------------------------------------------------------------------
__device__ __forceinline__ unsigned h2u(__half2 h) {
    return *reinterpret_cast<unsigned*>(&h);
}
__device__ __forceinline__ uint32_t smem_u32(const void* p) {
    uint32_t a;
    asm("{ .reg .u64 t; cvta.to.shared.u64 t, %1; cvt.u32.u64 %0, t; }"
        : "=r"(a) : "l"(p));
    return a;
}
__device__ __forceinline__ void cp16(uint32_t dst, const void* src) {
    asm volatile("cp.async.cg.shared.global [%0], [%1], 16;"
                 :: "r"(dst), "l"(src) : "memory");
}
__device__ __forceinline__ void cp_commit() {
    asm volatile("cp.async.commit_group;" ::: "memory");
}
__device__ __forceinline__ void ldmx4(uint32_t* r, uint32_t addr) {
    asm volatile("ldmatrix.sync.aligned.m8n8.x4.shared.b16 {%0,%1,%2,%3}, [%4];"
                 : "=r"(r[0]), "=r"(r[1]), "=r"(r[2]), "=r"(r[3]) : "r"(addr));
}
__device__ __forceinline__ void mma_f16(float* d, const uint32_t* a,
                                        uint32_t b0, uint32_t b1) {
    asm volatile(
        "mma.sync.aligned.m16n8k16.row.col.f32.f16.f16.f32 "
        "{%0,%1,%2,%3}, {%4,%5,%6,%7}, {%8,%9}, {%0,%1,%2,%3};"
        : "+f"(d[0]), "+f"(d[1]), "+f"(d[2]), "+f"(d[3])
        : "r"(a[0]), "r"(a[1]), "r"(a[2]), "r"(a[3]), "r"(b0), "r"(b1));
}

// ---------------------------------------------------------------------------
__global__ void k_style(const float* __restrict__ style, const float* __restrict__ mw,
                        const float* __restrict__ mb) {
    int b = blockIdx.x, i = threadIdx.x;
    __shared__ float st[SD];
    st[i] = style[b * SD + i];
    __syncthreads();
    const float* row = mw + (size_t)i * SD;
    float acc = 0.f;
#pragma unroll 4
    for (int j = 0; j < SD; j += 4) {
        float4 m = *(const float4*)(row + j);
        acc += m.x * st[j] + m.y * st[j + 1] + m.z * st[j + 2] + m.w * st[j + 3];
    }
    g_s[b * CI + i] = acc * 0.04419417382415922f + mb[i];
}

// Fused prep: wsplit (bid<256) | w2 (256..767) | xsplit (768..1023)
__global__ void __launch_bounds__(512)
k_prep(const float* __restrict__ cw, const float* __restrict__ x) {
    int bid = blockIdx.x, tid = threadIdx.x;
    if (bid < 256) {
        int idx = bid * 512 + tid;
        int o = idx >> 8, ipair = idx & 255;
        int i = ipair * 2;
        const float* p0 = cw + ((size_t)o * CI + i) * 9;
        const float* p1 = p0 + 9;
        unsigned* pk = (unsigned*)g_k;
#pragma unroll
        for (int k = 0; k < 9; ++k) {
            unsigned v = h2u(__floats2half2_rn(p0[k], p1[k]));
            pk[((size_t)k * CO + o) * (CI / 2) + ipair] = v;
        }
    } else if (bid < 768) {
        int idx = (bid - 256) * 512 + tid;
        const float* p = cw + (size_t)idx * 9;
        float a = 0.f;
#pragma unroll
        for (int k = 0; k < 9; ++k) a += p[k] * p[k];
        g_W2[idx] = a;
    } else {
        int xb = bid - 768;
        int b = xb >> 4;
        int y = (xb & 15) * 2 + (tid >> 8);
        int ipair = tid & 255;
        int i = ipair * 2;
        const float* s0 = x + ((size_t)(b * CI + i) * 32 + y) * 32;
        const float* s1 = s0 + 1024;
        float sv0 = g_s[b * CI + i], sv1 = g_s[b * CI + i + 1];
        unsigned pk[32];
#pragma unroll
        for (int q4 = 0; q4 < 8; ++q4) {
            float4 f0 = *(const float4*)(s0 + q4 * 4);
            float4 f1 = *(const float4*)(s1 + q4 * 4);
            pk[q4 * 4 + 0] = h2u(__floats2half2_rn(f0.x * sv0, f1.x * sv1));
            pk[q4 * 4 + 1] = h2u(__floats2half2_rn(f0.y * sv0, f1.y * sv1));
            pk[q4 * 4 + 2] = h2u(__floats2half2_rn(f0.z * sv0, f1.z * sv1));
            pk[q4 * 4 + 3] = h2u(__floats2half2_rn(f0.w * sv0, f1.w * sv1));
        }
        unsigned* px = (unsigned*)g_x;
        size_t rowbase = (size_t)(b * 32 + y) * 32 * (CI / 2) + (size_t)ipair;
#pragma unroll
        for (int q = 0; q < 32; ++q)
            px[rowbase + (size_t)q * (CI / 2)] = pk[q];
    }
}

// ---------------------------------------------------------------------------
// Persistent z GEMM (unchanged).
#define A_BYTES 131072
#define B_STG 16384

__global__ void __launch_bounds__(512, 1)
k_zgemm() {
    extern __shared__ __align__(1024) char smem[];
    const uint32_t sb = smem_u32(smem);
    const uint32_t bbase = sb + A_BYTES;

    const int tid = threadIdx.x;
    const int wid = tid >> 5, ln = tid & 31;
    const int rt = blockIdx.x % 36;
    const int bg = blockIdx.x / 36;
    const int tp = rt >> 2;
    const int o0 = (rt & 3) * 128;
    const int wm = wid & 3, wn = wid >> 2;
    const int g = ln >> 2, t4 = ln & 3;

    const char* gA = (const char*)g_k;
    const char* gB = (const char*)g_x;

    {
        int r = tid >> 2;
        uint32_t c = (uint32_t)(tid & 3) << 4;
        uint32_t sw = c ^ (uint32_t)((r & 6) << 3);
        const char* sA = gA + ((size_t)(tp * CO + o0 + r) * CI) * 2 + c;
        uint32_t dA = sb + (uint32_t)(r * 64) + sw;
#pragma unroll
        for (int kc = 0; kc < 16; ++kc)
            cp16(dA + kc * 8192, sA + kc * 64);
        cp_commit();
    }

    int brow[2];
    uint32_t bco[2], bdst[2];
#pragma unroll
    for (int j = 0; j < 2; ++j) {
        int id = tid + 512 * j;
        brow[j] = id >> 2;
        bco[j] = (uint32_t)(id & 3) << 4;
        bdst[j] = bbase + (uint32_t)(brow[j] * 64) +
                  (bco[j] ^ (uint32_t)((brow[j] & 6) << 3));
    }

    uint32_t aAddr[2], bAddr[4];
#pragma unroll
    for (int mt = 0; mt < 2; ++mt) {
        int mrow = wm * 32 + mt * 16 + (ln & 15);
        uint32_t hi = (uint32_t)(ln >> 4) << 4;
        aAddr[mt] = sb + (uint32_t)(mrow * 64) + (hi ^ (uint32_t)((mrow & 6) << 3));
    }
#pragma unroll
    for (int np = 0; np < 4; ++np) {
        int nrow = wn * 64 + np * 16 + ((ln >> 4) & 1) * 8 + (ln & 7);
        uint32_t hi = (uint32_t)((ln >> 3) & 1) << 4;
        bAddr[np] = bbase + (uint32_t)(nrow * 64) + (hi ^ (uint32_t)((nrow & 6) << 3));
    }

    float acc[2][8][4];
#pragma unroll
    for (int mt = 0; mt < 2; ++mt)
#pragma unroll
        for (int nt = 0; nt < 8; ++nt)
#pragma unroll
            for (int e = 0; e < 4; ++e) acc[mt][nt][e] = 0.f;

#pragma unroll
    for (int s = 0; s < 3; ++s) {
        int nt1 = s >> 4, ks1 = s & 15;
        int b1 = bg * 4 + (nt1 >> 2), nb1 = nt1 & 3;
        uint32_t so = (uint32_t)(s & 3) * B_STG;
        size_t base = ((size_t)(b1 * 1024 + nb1 * 256) * CI + ks1 * 32) * 2;
        cp16(bdst[0] + so, gB + base + (size_t)brow[0] * CI * 2 + bco[0]);
        cp16(bdst[1] + so, gB + base + (size_t)brow[1] * CI * 2 + bco[1]);
        cp_commit();
    }

#pragma unroll 1
    for (int gs = 0; gs < 256; ++gs) {
        asm volatile("cp.async.wait_group 2;" ::: "memory");
        __syncthreads();

        if (gs + 3 < 256) {
            int g1 = gs + 3;
            int nt1 = g1 >> 4, ks1 = g1 & 15;
            int b1 = bg * 4 + (nt1 >> 2), nb1 = nt1 & 3;
            uint32_t so = (uint32_t)(g1 & 3) * B_STG;
            size_t base = ((size_t)(b1 * 1024 + nb1 * 256) * CI + ks1 * 32) * 2;
            cp16(bdst[0] + so, gB + base + (size_t)brow[0] * CI * 2 + bco[0]);
            cp16(bdst[1] + so, gB + base + (size_t)brow[1] * CI * 2 + bco[1]);
        }
        cp_commit();

        const int ks = gs & 15;
        const uint32_t aOff = (uint32_t)(ks * 8192);
        const uint32_t bOff = (uint32_t)(gs & 3) * B_STG;
#pragma unroll
        for (int kt = 0; kt < 2; ++kt) {
            const uint32_t kx = (uint32_t)(kt << 5);
            uint32_t a[2][4];
            ldmx4(a[0], (aAddr[0] + aOff) ^ kx);
            ldmx4(a[1], (aAddr[1] + aOff) ^ kx);
#pragma unroll
            for (int np = 0; np < 4; ++np) {
                uint32_t bb[4];
                ldmx4(bb, (bAddr[np] + bOff) ^ kx);
                mma_f16(acc[0][2 * np],     a[0], bb[0], bb[1]);
                mma_f16(acc[0][2 * np + 1], a[0], bb[2], bb[3]);
                mma_f16(acc[1][2 * np],     a[1], bb[0], bb[1]);
                mma_f16(acc[1][2 * np + 1], a[1], bb[2], bb[3]);
            }
        }

        if (ks == 15) {
            int nt = gs >> 4;
            int b = bg * 4 + (nt >> 2), nblk = nt & 3;
#pragma unroll
            for (int mt = 0; mt < 2; ++mt)
#pragma unroll
                for (int rr = 0; rr < 2; ++rr) {
                    int o = o0 + wm * 32 + mt * 16 + rr * 8 + g;
                    __half2* zb = (__half2*)(g_z + ((size_t)(b * CO + o) * 9 + tp) * 1024);
#pragma unroll
                    for (int nt8 = 0; nt8 < 8; ++nt8) {
                        int nl = wn * 64 + nt8 * 8 + 2 * t4;
                        int sp = nblk * 256 + nl;
                        zb[sp >> 1] = __floats2half2_rn(acc[mt][nt8][rr * 2],
                                                        acc[mt][nt8][rr * 2 + 1]);
                    }
                }
#pragma unroll
            for (int mt = 0; mt < 2; ++mt)
#pragma unroll
                for (int nt8 = 0; nt8 < 8; ++nt8)
#pragma unroll
                    for (int e = 0; e < 4; ++e) acc[mt][nt8][e] = 0.f;
        }
    }
}

// ---------------------------------------------------------------------------
// Combine v2 (fixed scale): parity-paired stencils, padded smem, fused alpha.
// Stencil weights {1,3} carry a factored 1/4 per pass -> fold 1/16 into alp.
__global__ void __launch_bounds__(256)
k_comb(const float* __restrict__ noise, const float* __restrict__ nwp,
       const float* __restrict__ ab, float* __restrict__ out) {
    extern __shared__ float sm[];
    float* zs = sm;                 // 9*32*34 = 9792
    float* us = sm + 9792;          // 3*34*64 = 6528
    float* red = sm + 16320;        // 8

    const int bo = blockIdx.x;
    const int b = bo >> 9, o = bo & 511;
    const int tid = threadIdx.x;

    // fused alpha partial
    {
        float part = 0.f;
        const float* wrow = g_W2 + (size_t)o * CI;
        const float* srow = g_s + b * CI;
#pragma unroll
        for (int j = tid; j < CI; j += 256) {
            float sv = srow[j];
            part += sv * sv * wrow[j];
        }
#pragma unroll
        for (int off = 16; off; off >>= 1)
            part += __shfl_xor_sync(0xFFFFFFFFu, part, off);
        if ((tid & 31) == 0) red[tid >> 5] = part;
    }

    // stage z -> padded fp32 zs
    const __half2* zp2 = (const __half2*)(g_z + (size_t)bo * 9216);
#pragma unroll
    for (int j = tid; j < 4608; j += 256) {
        float2 f = __half22float2(zp2[j]);
        int e = 2 * j;
        int row = e >> 5;            // tap*32 + y
        int q = e & 31;              // even
        int idx = row * 34 + 1 + q;
        zs[idx] = f.x;
        zs[idx + 1] = f.y;
    }
    // halo zero: zs cols 0,33 of 288 rows; us rows pp=0,33 of 3 ky planes
#pragma unroll
    for (int j = tid; j < 576; j += 256)
        zs[(j >> 1) * 34 + (j & 1) * 33] = 0.f;
#pragma unroll
    for (int j = tid; j < 384; j += 256) {
        int r = j >> 6;              // 0..5
        us[((r >> 1) * 34 + (r & 1) * 33) * 64 + (j & 63)] = 0.f;
    }
    __syncthreads();

    float asum = red[0] + red[1] + red[2] + red[3] +
                 red[4] + red[5] + red[6] + red[7];
    // 1/16 folds the two factored-out 1/4 stencil scales (x-pass and y-pass)
    const float alp = 0.014731391274719739f *
                      rsqrtf(asum * (1.0f / 4608.0f) + 1e-8f) * 0.0625f;

    // x-pass: 3072 items (ky,y,q) -> u[2q], u[2q+1]
#pragma unroll 1
    for (int m = tid; m < 3072; m += 256) {
        int q = m & 31, y = (m >> 5) & 31, ky = m >> 10;
        const float* z0 = zs + ((ky * 3 + 0) * 32 + y) * 34 + q;   // kx=0
        const float* z1 = z0 + 32 * 34;                             // kx=1
        const float* z2 = z1 + 32 * 34;                             // kx=2
        float z01 = z0[1], z02 = z0[2];
        float z10 = z1[0], z11 = z1[1], z12 = z1[2];
        float z20 = z2[0], z21 = z2[1];
        float t3 = 3.0f * z11;
        float u0 = z10 + 3.0f * z20 + 3.0f * z01 + t3 + z21 + z02;
        float u1 = z20 + z01 + t3 + 3.0f * z21 + 3.0f * z02 + z12;
        float2 uv = make_float2(u0, u1);
        *(float2*)(us + (ky * 34 + y + 1) * 64 + 2 * q) = uv;
    }
    __syncthreads();

    // y-pass: 2048 items (p, X) -> out[2p][X], out[2p+1][X]
    const float bia = ab[o];
    const float nw = *nwp;
    const float* nzb = noise + b * 4096;
    float* ob = out + (size_t)bo * 4096;
#pragma unroll 1
    for (int m = tid; m < 2048; m += 256) {
        int X = m & 63, p = m >> 6;
        const float* v0 = us + (0 * 34 + p) * 64 + X;
        const float* v1 = us + (1 * 34 + p) * 64 + X;
        const float* v2 = us + (2 * 34 + p) * 64 + X;
        float a01 = v0[64], a02 = v0[128];
        float a10 = v1[0], a11 = v1[64], a12 = v1[128];
        float a20 = v2[0], a21 = v2[64];
        float t3 = 3.0f * a11;
        float o0v = a10 + 3.0f * a20 + 3.0f * a01 + t3 + a21 + a02;
        float o1v = a20 + a01 + t3 + 3.0f * a21 + 3.0f * a02 + a12;
        int j0 = (2 * p) * 64 + X;
        float r0 = o0v * alp + nw * __ldg(nzb + j0) + bia;
        float r1 = o1v * alp + nw * __ldg(nzb + j0 + 64) + bia;
        r0 = (r0 > 0.f ? r0 : 0.2f * r0) * 1.4142135623730951f;
        r1 = (r1 > 0.f ? r1 : 0.2f * r1) * 1.4142135623730951f;
        ob[j0] = r0;
        ob[j0 + 64] = r1;
    }
}

// ---------------------------------------------------------------------------
extern "C" void kernel_launch(void* const* d_in, const int* in_sizes, int n_in,
                              void* d_out, int out_size) {
    const float* x           = (const float*)d_in[0];
    const float* style       = (const float*)d_in[1];
    const float* noise       = (const float*)d_in[2];
    const float* conv_weight = (const float*)d_in[3];
    const float* mod_weight  = (const float*)d_in[4];
    const float* mod_bias    = (const float*)d_in[5];
    const float* noise_w     = (const float*)d_in[6];
    const float* act_bias    = (const float*)d_in[7];
    float* out = (float*)d_out;

    cudaFuncSetAttribute(k_zgemm, cudaFuncAttributeMaxDynamicSharedMemorySize,
                         A_BYTES + 4 * B_STG);
    cudaFuncSetAttribute(k_comb, cudaFuncAttributeMaxDynamicSharedMemorySize, 65312);

    k_style<<<NB, 512>>>(style, mod_weight, mod_bias);
    k_prep<<<1024, 512>>>(conv_weight, x);
    k_zgemm<<<144, 512, A_BYTES + 4 * B_STG>>>();
    k_comb<<<NB * CO, 256, 65312>>>(noise, noise_w, act_bias, out);
}

// round 12
// speedup vs baseline: 1.6592x; 1.0908x over previous
#include <cuda_runtime.h>
#include <cuda_fp16.h>
#include <cstdint>
#include <math.h>

#define NB 16
#define CI 512
#define CO 512
#define SD 512

// ---------------------------------------------------------------------------
__device__ float g_s[NB * CI];
__device__ float g_W2[CO * CI];
__device__ __half g_x[(size_t)NB * 32 * 32 * CI];   // [b][y][x][i] fp16, modulated
__device__ __half g_k[(size_t)9 * CO * CI];         // [tap][o][i] fp16
__device__ __half g_z[(size_t)NB * CO * 9 * 1024];  // [b][o][tap][32x32] fp16

// ---------------------------------------------------------------------------
__device__ __forceinline__ unsigned h2u(__half2 h) {
    return *reinterpret_cast<unsigned*>(&h);
}
__device__ __forceinline__ uint32_t smem_u32(const void* p) {
    uint32_t a;
    asm("{ .reg .u64 t; cvta.to.shared.u64 t, %1; cvt.u32.u64 %0, t; }"
        : "=r"(a) : "l"(p));
    return a;
}
__device__ __forceinline__ void cp16(uint32_t dst, const void* src) {
    asm volatile("cp.async.cg.shared.global [%0], [%1], 16;"
                 :: "r"(dst), "l"(src) : "memory");
}
__device__ __forceinline__ void cp_commit() {
    asm volatile("cp.async.commit_group;" ::: "memory");
}
__device__ __forceinline__ void ldmx4(uint32_t* r, uint32_t addr) {
    asm volatile("ldmatrix.sync.aligned.m8n8.x4.shared.b16 {%0,%1,%2,%3}, [%4];"
                 : "=r"(r[0]), "=r"(r[1]), "=r"(r[2]), "=r"(r[3]) : "r"(addr));
}
__device__ __forceinline__ void mma_f16(float* d, const uint32_t* a,
                                        uint32_t b0, uint32_t b1) {
    asm volatile(
        "mma.sync.aligned.m16n8k16.row.col.f32.f16.f16.f32 "
        "{%0,%1,%2,%3}, {%4,%5,%6,%7}, {%8,%9}, {%0,%1,%2,%3};"
        : "+f"(d[0]), "+f"(d[1]), "+f"(d[2]), "+f"(d[3])
        : "r"(a[0]), "r"(a[1]), "r"(a[2]), "r"(a[3]), "r"(b0), "r"(b1));
}

// ---------------------------------------------------------------------------
__global__ void k_style(const float* __restrict__ style, const float* __restrict__ mw,
                        const float* __restrict__ mb) {
    int b = blockIdx.x, i = threadIdx.x;
    __shared__ float st[SD];
    st[i] = style[b * SD + i];
    __syncthreads();
    const float* row = mw + (size_t)i * SD;
    float acc = 0.f;
#pragma unroll 4
    for (int j = 0; j < SD; j += 4) {
        float4 m = *(const float4*)(row + j);
        acc += m.x * st[j] + m.y * st[j + 1] + m.z * st[j + 2] + m.w * st[j + 3];
    }
    g_s[b * CI + i] = acc * 0.04419417382415922f + mb[i];
}

// prep_w: wsplit (bid<256) | w2 (256..767)
__global__ void __launch_bounds__(512)
k_prep_w(const float* __restrict__ cw) {
    int bid = blockIdx.x, tid = threadIdx.x;
    if (bid < 256) {
        int idx = bid * 512 + tid;
        int o = idx >> 8, ipair = idx & 255;
        int i = ipair * 2;
        const float* p0 = cw + ((size_t)o * CI + i) * 9;
        const float* p1 = p0 + 9;
        unsigned* pk = (unsigned*)g_k;
#pragma unroll
        for (int k = 0; k < 9; ++k) {
            unsigned v = h2u(__floats2half2_rn(p0[k], p1[k]));
            pk[((size_t)k * CO + o) * (CI / 2) + ipair] = v;
        }
    } else {
        int idx = (bid - 256) * 512 + tid;
        const float* p = cw + (size_t)idx * 9;
        float a = 0.f;
#pragma unroll
        for (int k = 0; k < 9; ++k) a += p[k] * p[k];
        g_W2[idx] = a;
    }
}

// prep_x: g_x[b,y,q,i] = fp16(x[b,i,y,q] * s[b,i])
__global__ void __launch_bounds__(512)
k_prep_x(const float* __restrict__ x) {
    int xb = blockIdx.x, tid = threadIdx.x;
    int b = xb >> 4;
    int y = (xb & 15) * 2 + (tid >> 8);
    int ipair = tid & 255;
    int i = ipair * 2;
    const float* s0 = x + ((size_t)(b * CI + i) * 32 + y) * 32;
    const float* s1 = s0 + 1024;
    float sv0 = g_s[b * CI + i], sv1 = g_s[b * CI + i + 1];
    unsigned pk[32];
#pragma unroll
    for (int q4 = 0; q4 < 8; ++q4) {
        float4 f0 = *(const float4*)(s0 + q4 * 4);
        float4 f1 = *(const float4*)(s1 + q4 * 4);
        pk[q4 * 4 + 0] = h2u(__floats2half2_rn(f0.x * sv0, f1.x * sv1));
        pk[q4 * 4 + 1] = h2u(__floats2half2_rn(f0.y * sv0, f1.y * sv1));
        pk[q4 * 4 + 2] = h2u(__floats2half2_rn(f0.z * sv0, f1.z * sv1));
        pk[q4 * 4 + 3] = h2u(__floats2half2_rn(f0.w * sv0, f1.w * sv1));
    }
    unsigned* px = (unsigned*)g_x;
    size_t rowbase = (size_t)(b * 32 + y) * 32 * (CI / 2) + (size_t)ipair;
#pragma unroll
    for (int q = 0; q < 32; ++q)
        px[rowbase + (size_t)q * (CI / 2)] = pk[q];
}

// ---------------------------------------------------------------------------
// Persistent z GEMM v3: 144 CTAs, 256 threads / 8 warps, warp tile 64x64.
// A resident (128KB), B 4-deep ring (4x16KB). Fragments for both k-chunks
// loaded up front; MMAs issued as one unbroken stream.
#define A_BYTES 131072
#define B_STG 16384

__global__ void __launch_bounds__(256, 1)
k_zgemm() {
    extern __shared__ __align__(1024) char smem[];
    const uint32_t sb = smem_u32(smem);
    const uint32_t bbase = sb + A_BYTES;

    const int tid = threadIdx.x;
    const int wid = tid >> 5, ln = tid & 31;
    const int rt = blockIdx.x % 36;
    const int bg = blockIdx.x / 36;
    const int tp = rt >> 2;
    const int o0 = (rt & 3) * 128;
    const int wm = wid & 1, wn = wid >> 1;
    const int g = ln >> 2, t4 = ln & 3;

    const char* gA = (const char*)g_k;
    const char* gB = (const char*)g_x;

    // --- load full A (128 x 512 fp16 = 128KB) ---
    {
        int r = tid >> 2;                        // 0..63
        uint32_t c = (uint32_t)(tid & 3) << 4;
        const char* sA0 = gA + ((size_t)(tp * CO + o0 + r) * CI) * 2 + c;
        const char* sA1 = gA + ((size_t)(tp * CO + o0 + r + 64) * CI) * 2 + c;
        uint32_t dA0 = sb + (uint32_t)(r * 64) + (c ^ (uint32_t)((r & 6) << 3));
        int r1 = r + 64;
        uint32_t dA1 = sb + (uint32_t)(r1 * 64) + (c ^ (uint32_t)((r1 & 6) << 3));
#pragma unroll
        for (int kc = 0; kc < 16; ++kc) {
            cp16(dA0 + kc * 8192, sA0 + kc * 64);
            cp16(dA1 + kc * 8192, sA1 + kc * 64);
        }
        cp_commit();
    }

    // --- B stage setup: 4 chunks of 16B per thread per stage (16KB total) ---
    int brow[4];
    uint32_t bco[4], bdst[4];
#pragma unroll
    for (int j = 0; j < 4; ++j) {
        int id = tid + 256 * j;
        brow[j] = id >> 2;                       // 0..255
        bco[j] = (uint32_t)(id & 3) << 4;
        bdst[j] = bbase + (uint32_t)(brow[j] * 64) +
                  (bco[j] ^ (uint32_t)((brow[j] & 6) << 3));
    }

    // --- ldmatrix fragment addresses ---
    uint32_t aAddr[4], bAddr[4];
#pragma unroll
    for (int mt = 0; mt < 4; ++mt) {
        int mrow = wm * 64 + mt * 16 + (ln & 15);
        uint32_t hi = (uint32_t)(ln >> 4) << 4;
        aAddr[mt] = sb + (uint32_t)(mrow * 64) + (hi ^ (uint32_t)((mrow & 6) << 3));
    }
#pragma unroll
    for (int np = 0; np < 4; ++np) {
        int nrow = wn * 64 + np * 16 + ((ln >> 4) & 1) * 8 + (ln & 7);
        uint32_t hi = (uint32_t)((ln >> 3) & 1) << 4;
        bAddr[np] = bbase + (uint32_t)(nrow * 64) + (hi ^ (uint32_t)((nrow & 6) << 3));
    }

    float acc[4][8][4];
#pragma unroll
    for (int mt = 0; mt < 4; ++mt)
#pragma unroll
        for (int nt = 0; nt < 8; ++nt)
#pragma unroll
            for (int e = 0; e < 4; ++e) acc[mt][nt][e] = 0.f;

    // --- prologue: B stages 0..2 ---
#pragma unroll
    for (int s = 0; s < 3; ++s) {
        int nt1 = s >> 4, ks1 = s & 15;
        int b1 = bg * 4 + (nt1 >> 2), nb1 = nt1 & 3;
        uint32_t so = (uint32_t)(s & 3) * B_STG;
        size_t base = ((size_t)(b1 * 1024 + nb1 * 256) * CI + ks1 * 32) * 2;
#pragma unroll
        for (int j = 0; j < 4; ++j)
            cp16(bdst[j] + so, gB + base + (size_t)brow[j] * CI * 2 + bco[j]);
        cp_commit();
    }

#pragma unroll 1
    for (int gs = 0; gs < 256; ++gs) {
        asm volatile("cp.async.wait_group 2;" ::: "memory");
        __syncthreads();

        if (gs + 3 < 256) {
            int g1 = gs + 3;
            int nt1 = g1 >> 4, ks1 = g1 & 15;
            int b1 = bg * 4 + (nt1 >> 2), nb1 = nt1 & 3;
            uint32_t so = (uint32_t)(g1 & 3) * B_STG;
            size_t base = ((size_t)(b1 * 1024 + nb1 * 256) * CI + ks1 * 32) * 2;
#pragma unroll
            for (int j = 0; j < 4; ++j)
                cp16(bdst[j] + so, gB + base + (size_t)brow[j] * CI * 2 + bco[j]);
        }
        cp_commit();

        const int ks = gs & 15;
        const uint32_t aOff = (uint32_t)(ks * 8192);
        const uint32_t bOff = (uint32_t)(gs & 3) * B_STG;

        // load ALL fragments (both k-chunks) first, then unbroken MMA stream
        uint32_t fa[2][4][4], fb[2][4][4];
#pragma unroll
        for (int kt = 0; kt < 2; ++kt) {
            const uint32_t kx = (uint32_t)(kt << 5);
#pragma unroll
            for (int mt = 0; mt < 4; ++mt)
                ldmx4(fa[kt][mt], (aAddr[mt] + aOff) ^ kx);
#pragma unroll
            for (int np = 0; np < 4; ++np)
                ldmx4(fb[kt][np], (bAddr[np] + bOff) ^ kx);
        }
#pragma unroll
        for (int kt = 0; kt < 2; ++kt)
#pragma unroll
            for (int np = 0; np < 4; ++np)
#pragma unroll
                for (int mt = 0; mt < 4; ++mt) {
                    mma_f16(acc[mt][2 * np],     fa[kt][mt], fb[kt][np][0], fb[kt][np][1]);
                    mma_f16(acc[mt][2 * np + 1], fa[kt][mt], fb[kt][np][2], fb[kt][np][3]);
                }

        if (ks == 15) {
            int nt = gs >> 4;
            int b = bg * 4 + (nt >> 2), nblk = nt & 3;
#pragma unroll
            for (int mt = 0; mt < 4; ++mt)
#pragma unroll
                for (int rr = 0; rr < 2; ++rr) {
                    int o = o0 + wm * 64 + mt * 16 + rr * 8 + g;
                    __half2* zb = (__half2*)(g_z + ((size_t)(b * CO + o) * 9 + tp) * 1024);
#pragma unroll
                    for (int nt8 = 0; nt8 < 8; ++nt8) {
                        int nl = wn * 64 + nt8 * 8 + 2 * t4;
                        int sp = nblk * 256 + nl;
                        zb[sp >> 1] = __floats2half2_rn(acc[mt][nt8][rr * 2],
                                                        acc[mt][nt8][rr * 2 + 1]);
                    }
                }
#pragma unroll
            for (int mt = 0; mt < 4; ++mt)
#pragma unroll
                for (int nt8 = 0; nt8 < 8; ++nt8)
#pragma unroll
                    for (int e = 0; e < 4; ++e) acc[mt][nt8][e] = 0.f;
        }
    }
}

// ---------------------------------------------------------------------------
// Combine v3: vectorized parity-quad stencils, aligned float2/float4 smem.
// zs: stride 36, data at padded col 2+c (c=0..31); halo cols {0,1,34,35}.
// us: stride 64, rows pp=y+1, halo pp {0,33}.
__global__ void __launch_bounds__(256)
k_comb(const float* __restrict__ noise, const float* __restrict__ nwp,
       const float* __restrict__ ab, float* __restrict__ out) {
    extern __shared__ float sm[];
    float* zs = sm;                 // 288*36 = 10368
    float* us = sm + 10368;         // 3*34*64 = 6528
    float* red = sm + 16896;        // 8

    const int bo = blockIdx.x;
    const int b = bo >> 9, o = bo & 511;
    const int tid = threadIdx.x;

    // fused alpha partial
    {
        float part = 0.f;
        const float* wrow = g_W2 + (size_t)o * CI;
        const float* srow = g_s + b * CI;
#pragma unroll
        for (int j = tid; j < CI; j += 256) {
            float sv = srow[j];
            part += sv * sv * wrow[j];
        }
#pragma unroll
        for (int off = 16; off; off >>= 1)
            part += __shfl_xor_sync(0xFFFFFFFFu, part, off);
        if ((tid & 31) == 0) red[tid >> 5] = part;
    }

    // stage z -> padded fp32 zs (float2 stores, aligned)
    const __half2* zp2 = (const __half2*)(g_z + (size_t)bo * 9216);
#pragma unroll
    for (int j = tid; j < 4608; j += 256) {
        float2 f = __half22float2(zp2[j]);
        int e = 2 * j;
        int row = e >> 5;            // tap*32 + y
        int q = e & 31;              // even
        *(float2*)(zs + row * 36 + 2 + q) = f;
    }
    // halos: zs col pairs {0,1} and {34,35}; us rows pp=0,33
#pragma unroll
    for (int j = tid; j < 576; j += 256) {
        int row = j >> 1;
        *(float2*)(zs + row * 36 + (j & 1) * 34) = make_float2(0.f, 0.f);
    }
#pragma unroll
    for (int j = tid; j < 192; j += 256) {
        int r = j >> 5;              // 0..5
        int xx = (j & 31) * 2;
        *(float2*)(us + ((r >> 1) * 34 + (r & 1) * 33) * 64 + xx) = make_float2(0.f, 0.f);
    }
    __syncthreads();

    float asum = red[0] + red[1] + red[2] + red[3] +
                 red[4] + red[5] + red[6] + red[7];
    const float alp = 0.014731391274719739f *
                      rsqrtf(asum * (1.0f / 4608.0f) + 1e-8f) * 0.0625f;

    // x-pass: 1536 items, each -> u[4qq..4qq+3] (float4 store)
#pragma unroll 1
    for (int m = tid; m < 1536; m += 256) {
        int qq = m & 15, y = (m >> 4) & 31, ky = m >> 9;
        const float* r0 = zs + ((ky * 3 + 0) * 32 + y) * 36 + 2 * qq;
        const float* r1 = r0 + 32 * 36;
        const float* r2 = r1 + 32 * 36;
        float2 A0 = *(const float2*)r0, B0 = *(const float2*)(r0 + 2),
               C0 = *(const float2*)(r0 + 4);
        float2 A1 = *(const float2*)r1, B1 = *(const float2*)(r1 + 2),
               C1 = *(const float2*)(r1 + 4);
        float2 A2 = *(const float2*)r2, B2 = *(const float2*)(r2 + 2),
               C2 = *(const float2*)(r2 + 4);
        // p=c-1 (A.y), r=c (B.x), s=c+1 (B.y), t=c+2 (C.x) per kx
        float p1 = A1.y, p2 = A2.y;
        float q0 = B0.x, q1 = B1.x, q2 = B2.x;
        float s0 = B0.y, s1 = B1.y, s2 = B2.y;
        float t0 = C0.x, t1 = C1.x;
        float4 u;
        u.x = p1 + 3.f * p2 + 3.f * q0 + 3.f * q1 + q2 + s0;
        u.y = p2 + q0 + 3.f * q1 + 3.f * q2 + 3.f * s0 + s1;
        u.z = q1 + 3.f * q2 + 3.f * s0 + 3.f * s1 + s2 + t0;
        u.w = q2 + s0 + 3.f * s1 + 3.f * s2 + 3.f * t0 + t1;
        *(float4*)(us + (ky * 34 + y + 1) * 64 + 4 * qq) = u;
    }
    __syncthreads();

    // y-pass: 1024 items, each -> out rows 2p,2p+1 at cols X2,X2+1
    const float bia = ab[o];
    const float nw = *nwp;
    const float* nzb = noise + b * 4096;
    float* ob = out + (size_t)bo * 4096;
#pragma unroll 1
    for (int m = tid; m < 1024; m += 256) {
        int X2 = (m & 31) * 2, p = m >> 5;
        const float* v0 = us + (0 * 34 + p) * 64 + X2;
        const float* v1 = us + (1 * 34 + p) * 64 + X2;
        const float* v2 = us + (2 * 34 + p) * 64 + X2;
        float2 a01 = *(const float2*)(v0 + 64), a02 = *(const float2*)(v0 + 128);
        float2 a10 = *(const float2*)(v1),      a11 = *(const float2*)(v1 + 64);
        float2 a12 = *(const float2*)(v1 + 128);
        float2 a20 = *(const float2*)(v2),      a21 = *(const float2*)(v2 + 64);
        float2 o0v, o1v;
        o0v.x = a10.x + 3.f * a20.x + 3.f * a01.x + 3.f * a11.x + a21.x + a02.x;
        o0v.y = a10.y + 3.f * a20.y + 3.f * a01.y + 3.f * a11.y + a21.y + a02.y;
        o1v.x = a20.x + a01.x + 3.f * a11.x + 3.f * a21.x + 3.f * a02.x + a12.x;
        o1v.y = a20.y + a01.y + 3.f * a11.y + 3.f * a21.y + 3.f * a02.y + a12.y;
        int j0 = (2 * p) * 64 + X2;
        float2 n0 = *(const float2*)(nzb + j0);
        float2 n1 = *(const float2*)(nzb + j0 + 64);
        float2 w0, w1;
        w0.x = o0v.x * alp + nw * n0.x + bia;
        w0.y = o0v.y * alp + nw * n0.y + bia;
        w1.x = o1v.x * alp + nw * n1.x + bia;
        w1.y = o1v.y * alp + nw * n1.y + bia;
        w0.x = (w0.x > 0.f ? w0.x : 0.2f * w0.x) * 1.4142135623730951f;
        w0.y = (w0.y > 0.f ? w0.y : 0.2f * w0.y) * 1.4142135623730951f;
        w1.x = (w1.x > 0.f ? w1.x : 0.2f * w1.x) * 1.4142135623730951f;
        w1.y = (w1.y > 0.f ? w1.y : 0.2f * w1.y) * 1.4142135623730951f;
        *(float2*)(ob + j0) = w0;
        *(float2*)(ob + j0 + 64) = w1;
    }
}

// ---------------------------------------------------------------------------
extern "C" void kernel_launch(void* const* d_in, const int* in_sizes, int n_in,
                              void* d_out, int out_size) {
    const float* x           = (const float*)d_in[0];
    const float* style       = (const float*)d_in[1];
    const float* noise       = (const float*)d_in[2];
    const float* conv_weight = (const float*)d_in[3];
    const float* mod_weight  = (const float*)d_in[4];
    const float* mod_bias    = (const float*)d_in[5];
    const float* noise_w     = (const float*)d_in[6];
    const float* act_bias    = (const float*)d_in[7];
    float* out = (float*)d_out;

    cudaFuncSetAttribute(k_zgemm, cudaFuncAttributeMaxDynamicSharedMemorySize,
                         A_BYTES + 4 * B_STG);
    cudaFuncSetAttribute(k_comb, cudaFuncAttributeMaxDynamicSharedMemorySize, 67648);

    // zgemm at launch index 3 -> lands in the ncu capture window.
    k_style<<<NB, 512>>>(style, mod_weight, mod_bias);
    k_prep_w<<<768, 512>>>(conv_weight);
    k_prep_x<<<256, 512>>>(x);
    k_zgemm<<<144, 256, A_BYTES + 4 * B_STG>>>();
    k_comb<<<NB * CO, 256, 67648>>>(noise, noise_w, act_bias, out);
}